// round 7
// baseline (speedup 1.0000x reference)
#include <cuda_runtime.h>
#include <math.h>

// ---------------------------------------------------------------------------
// SE4: 4x4-patch squeeze-excite, group-pipelined for L2 reuse (no cross-role
// sync; only a 32-block peer spin inside the tiny MLP kernel).
//   t: [B=8, C=64, H=256, W=256] fp32 (134 MB), L2 = 126 MB.
//   Groups: G0={0,1,2}, G1={3,4,5}, G2={6,7} (50+50+34 MB).
//   pool(G0) ; mlp(G0) ; [gate(G0) || pool(G1)] ; mlp(G1) ;
//   [gate(G1) || pool(G2)] ; mlp(G2) ; gate(G2)
//   gate(Gk) reads t(Gk) from L2 (pooled one kernel earlier), streams writes.
//   DRAM total ~= 268 MB vs 402 MB for the two-pass structure.
// ---------------------------------------------------------------------------

#define B_   8
#define C_   64
#define H_   256
#define W_   256
#define SQ_  256
#define GC_  1024
#define NPOOL (B_ * GC_)
#define NT   256
#define BATCH_F4 (C_ * H_ * W_ / 4)       // 2^20 float4 per batch
#define GATE_BLOCKS 1024
#define MLP_BLOCKS 32

__device__ float g_ph0[NPOOL];      // half-patch raw sums (rows 0-31)
__device__ float g_ph1[NPOOL];      // half-patch raw sums (rows 32-63)
__device__ float g_s[B_ * SQ_];
__device__ float g_gates[NPOOL];
__device__ int   g_cnt[4];

// ---------------------------------------------------------------------------
__device__ __forceinline__ float mishf(float x) {
    float sp = (x > 20.0f) ? x : log1pf(__expf(x));
    return x * tanhf(sp);
}
__device__ __forceinline__ float sigmoidf_(float x) {
    return 1.0f / (1.0f + __expf(-x));
}

// Pool one half-patch (32 rows x 64 cols) per warp. pw in [0, nb*2048).
__device__ __forceinline__ void pool_half_warp(const float* __restrict__ t,
                                               int b0, int pw, int lane) {
    int b    = b0 + (pw >> 11);
    int rem  = pw & 2047;
    int half = rem & 1;
    int p    = rem >> 1;            // 0..1023
    int c    = p >> 4;
    int ij   = p & 15;
    int i    = ij >> 2;
    int j    = ij & 3;

    const float* base = t + (((size_t)(b * C_ + c) * H_ + i * 64 + half * 32) * W_ + j * 64);
    const float* q = base + (size_t)(lane >> 4) * W_ + (lane & 15) * 4;

    float a0 = 0.f, a1 = 0.f, a2 = 0.f, a3 = 0.f;
#pragma unroll
    for (int it = 0; it < 4; ++it) {
        float4 v0 = *reinterpret_cast<const float4*>(q + (size_t)(it * 8 + 0) * W_);
        float4 v1 = *reinterpret_cast<const float4*>(q + (size_t)(it * 8 + 2) * W_);
        float4 v2 = *reinterpret_cast<const float4*>(q + (size_t)(it * 8 + 4) * W_);
        float4 v3 = *reinterpret_cast<const float4*>(q + (size_t)(it * 8 + 6) * W_);
        a0 += (v0.x + v0.y) + (v0.z + v0.w);
        a1 += (v1.x + v1.y) + (v1.z + v1.w);
        a2 += (v2.x + v2.y) + (v2.z + v2.w);
        a3 += (v3.x + v3.y) + (v3.z + v3.w);
    }
    float acc = (a0 + a1) + (a2 + a3);
#pragma unroll
    for (int off = 16; off > 0; off >>= 1)
        acc += __shfl_down_sync(0xFFFFFFFFu, acc, off);
    if (lane == 0) {
        float* dst = half ? g_ph1 : g_ph0;
        dst[b * GC_ + ij * C_ + c] = acc;   // raw sum; /4096 in mlp stage 1
    }
}

// ---------------------------------------------------------------------------
// K1: pool group 0 (half patches) + zero spin counters.
// grid = nb*256 blocks (768 for nb=3).
// ---------------------------------------------------------------------------
__global__ void __launch_bounds__(NT) se4_pool0(const float* __restrict__ t) {
    if (blockIdx.x == 0 && threadIdx.x < 4) g_cnt[threadIdx.x] = 0;
    pool_half_warp(t, 0, blockIdx.x * 8 + (threadIdx.x >> 5), threadIdx.x & 31);
}

// ---------------------------------------------------------------------------
// K: fused MLP for batches [b0, b0+nb). Exactly MLP_BLOCKS=32 blocks (all
// resident -> the stage1/stage2 spin among peers is deadlock-free).
// stage1: warp (bid*8+w) computes s[b, wg] for all nb batches.
// stage2: 4 outputs per warp x nb batches.
// ---------------------------------------------------------------------------
__global__ void __launch_bounds__(NT) se4_mlp(const float* __restrict__ reduce_w,
                                              const float* __restrict__ reduce_b,
                                              const float* __restrict__ expand_w,
                                              const float* __restrict__ expand_b,
                                              int b0, int nb, int gidx) {
    int lane = threadIdx.x & 31;
    int wg   = blockIdx.x * 8 + (threadIdx.x >> 5);   // 0..255

    // ---- stage 1 ----
    {
        const float4* wrow = reinterpret_cast<const float4*>(reduce_w + (size_t)wg * GC_);
        for (int bb = 0; bb < nb; ++bb) {
            int b = b0 + bb;
            const float4* p0 = reinterpret_cast<const float4*>(g_ph0 + (size_t)b * GC_);
            const float4* p1 = reinterpret_cast<const float4*>(g_ph1 + (size_t)b * GC_);
            float acc = 0.0f;
#pragma unroll
            for (int k4 = lane; k4 < GC_ / 4; k4 += 32) {
                float4 wv = wrow[k4];
                float4 x0 = p0[k4];
                float4 x1 = p1[k4];
                acc += wv.x * (x0.x + x1.x) + wv.y * (x0.y + x1.y)
                     + wv.z * (x0.z + x1.z) + wv.w * (x0.w + x1.w);
            }
#pragma unroll
            for (int off = 16; off > 0; off >>= 1)
                acc += __shfl_down_sync(0xFFFFFFFFu, acc, off);
            if (lane == 0)
                g_s[b * SQ_ + wg] = mishf(acc * (1.0f / 4096.0f) + reduce_b[wg]);
        }
    }
    __threadfence();
    __syncthreads();
    if (threadIdx.x == 0) {
        atomicAdd(&g_cnt[gidx], 1);
        volatile int* v = &g_cnt[gidx];
        while (*v < MLP_BLOCKS) __nanosleep(32);
    }
    __syncthreads();

    // ---- stage 2 ----
#pragma unroll
    for (int qq = 0; qq < 4; ++qq) {
        int o = wg + qq * 256;
        const float4* erow = reinterpret_cast<const float4*>(expand_w + (size_t)o * SQ_);
        for (int bb = 0; bb < nb; ++bb) {
            int b = b0 + bb;
            const float4* srow = reinterpret_cast<const float4*>(g_s + (size_t)b * SQ_);
            float acc = 0.0f;
#pragma unroll
            for (int k4 = lane; k4 < SQ_ / 4; k4 += 32) {
                float4 wv = erow[k4];
                float4 sv = __ldcg(srow + k4);
                acc += wv.x * sv.x + wv.y * sv.y + wv.z * sv.z + wv.w * sv.w;
            }
#pragma unroll
            for (int off = 16; off > 0; off >>= 1)
                acc += __shfl_down_sync(0xFFFFFFFFu, acc, off);
            if (lane == 0)
                g_gates[b * GC_ + o] = sigmoidf_(acc + expand_b[o]);
        }
    }
}

// ---------------------------------------------------------------------------
// K: gatepool — two independent roles, no synchronization.
//   blocks [0, pool_nb*256): pool batches [pool_b0, ..) half-patches (DRAM,
//     default policy -> fills L2 for the NEXT gatepool kernel)
//   blocks [pool_nb*256, +1024): gate batches [gate_b0, ..). Each thread
//     handles one 64B chunk (4 consecutive float4) sharing a single gate
//     value. Reads .cs (L2-resident, demote after use), writes .stcs.
// ---------------------------------------------------------------------------
__global__ void __launch_bounds__(NT) se4_gatepool(const float* __restrict__ t,
                                                   float* __restrict__ out,
                                                   int gate_b0, int gate_nb,
                                                   int pool_b0, int pool_nb) {
    int poolBlocks = pool_nb * 256;

    if ((int)blockIdx.x < poolBlocks) {
        pool_half_warp(t, pool_b0, blockIdx.x * 8 + (threadIdx.x >> 5),
                       threadIdx.x & 31);
        return;
    }

    // ---- gate role: one 64B chunk (4 float4) per thread per iteration ----
    int gb = blockIdx.x - poolBlocks;                 // 0..1023
    const float4* tb = reinterpret_cast<const float4*>(t)  + (size_t)gate_b0 * BATCH_F4;
    float4*       ob = reinterpret_cast<float4*>(out)      + (size_t)gate_b0 * BATCH_F4;
    const float*  gbase = g_gates + gate_b0 * GC_;
    const size_t total_chunks = (size_t)gate_nb * (BATCH_F4 / 4);
    const size_t S = (size_t)GATE_BLOCKS * NT;        // 262144 chunks/sweep

    for (size_t ch = (size_t)gb * NT + threadIdx.x; ch < total_chunks; ch += S) {
        size_t b4 = ch * 4;                           // float4 index of chunk
        // layout of b4: [b_local][c(6)][h(8)][w4(6)]
        int w4 = (int)(b4 & 63);
        int h  = (int)(b4 >> 6) & 255;
        int c  = (int)(b4 >> 14) & 63;
        int bl = (int)(b4 >> 20);
        float gg = __ldg(gbase + bl * 1024 + (h >> 6) * 256 + (w4 >> 4) * 64 + c);

        float4 v0 = __ldcs(tb + b4 + 0);
        float4 v1 = __ldcs(tb + b4 + 1);
        float4 v2 = __ldcs(tb + b4 + 2);
        float4 v3 = __ldcs(tb + b4 + 3);
        v0.x *= gg; v0.y *= gg; v0.z *= gg; v0.w *= gg;
        v1.x *= gg; v1.y *= gg; v1.z *= gg; v1.w *= gg;
        v2.x *= gg; v2.y *= gg; v2.z *= gg; v2.w *= gg;
        v3.x *= gg; v3.y *= gg; v3.z *= gg; v3.w *= gg;
        __stcs(ob + b4 + 0, v0);
        __stcs(ob + b4 + 1, v1);
        __stcs(ob + b4 + 2, v2);
        __stcs(ob + b4 + 3, v3);
    }
}

// ---------------------------------------------------------------------------
extern "C" void kernel_launch(void* const* d_in, const int* in_sizes, int n_in,
                              void* d_out, int out_size) {
    const float* t        = (const float*)d_in[0];
    const float* reduce_w = (const float*)d_in[1];
    const float* reduce_b = (const float*)d_in[2];
    const float* expand_w = (const float*)d_in[3];
    const float* expand_b = (const float*)d_in[4];
    float* out = (float*)d_out;

    // Groups: G0 = {0,1,2}, G1 = {3,4,5}, G2 = {6,7}
    se4_pool0<<<3 * 256, NT>>>(t);
    se4_mlp<<<MLP_BLOCKS, NT>>>(reduce_w, reduce_b, expand_w, expand_b, 0, 3, 0);
    se4_gatepool<<<3 * 256 + GATE_BLOCKS, NT>>>(t, out, 0, 3, 3, 3);
    se4_mlp<<<MLP_BLOCKS, NT>>>(reduce_w, reduce_b, expand_w, expand_b, 3, 3, 1);
    se4_gatepool<<<2 * 256 + GATE_BLOCKS, NT>>>(t, out, 3, 3, 6, 2);
    se4_mlp<<<MLP_BLOCKS, NT>>>(reduce_w, reduce_b, expand_w, expand_b, 6, 2, 2);
    se4_gatepool<<<GATE_BLOCKS, NT>>>(t, out, 6, 2, 0, 0);
}

// round 8
// speedup vs baseline: 1.3292x; 1.3292x over previous
#include <cuda_runtime.h>
#include <math.h>

// ---------------------------------------------------------------------------
// SE4: 4x4-patch squeeze-excite, group-pipelined for L2 reuse.
//   t: [B=8, C=64, H=256, W=256] fp32 (134 MB), L2 = 126 MB.
//   Groups: G0={0,1,2}, G1={3,4,5}, G2={6,7} (50+50+34 MB).
//   pool(G0); mlp1(G0); mlp2(G0); [gate(G0)||pool(G1)]; mlp1(G1); mlp2(G1);
//   [gate(G1)||pool(G2)]; mlp1(G2); mlp2(G2); gate(G2)
//   gate(Gk) reads t(Gk) from L2 (pooled one kernel earlier, .cs demote),
//   streams writes (.stcs). DRAM ~= 268 MB vs 402 MB two-pass.
//   NO intra-kernel synchronization anywhere (rounds 4/5/7 proved spins lose).
// ---------------------------------------------------------------------------

#define B_   8
#define C_   64
#define H_   256
#define W_   256
#define SQ_  256
#define GC_  1024
#define NPOOL (B_ * GC_)
#define NT   256
#define BATCH_F4 (C_ * H_ * W_ / 4)       // 2^20 float4 per batch

__device__ float g_ph0[NPOOL];      // half-patch raw sums (rows 0-31)
__device__ float g_ph1[NPOOL];      // half-patch raw sums (rows 32-63)
__device__ float g_s[B_ * SQ_];
__device__ float g_gates[NPOOL];

// ---------------------------------------------------------------------------
__device__ __forceinline__ float mishf(float x) {
    float sp = (x > 20.0f) ? x : log1pf(__expf(x));
    return x * tanhf(sp);
}
__device__ __forceinline__ float sigmoidf_(float x) {
    return 1.0f / (1.0f + __expf(-x));
}

// Pool one half-patch (32 rows x 64 cols) per warp. pw in [0, nb*2048).
__device__ __forceinline__ void pool_half_warp(const float* __restrict__ t,
                                               int b0, int pw, int lane) {
    int b    = b0 + (pw >> 11);
    int rem  = pw & 2047;
    int half = rem & 1;
    int p    = rem >> 1;            // 0..1023
    int c    = p >> 4;
    int ij   = p & 15;
    int i    = ij >> 2;
    int j    = ij & 3;

    const float* base = t + (((size_t)(b * C_ + c) * H_ + i * 64 + half * 32) * W_ + j * 64);
    const float* q = base + (size_t)(lane >> 4) * W_ + (lane & 15) * 4;

    float a0 = 0.f, a1 = 0.f, a2 = 0.f, a3 = 0.f;
#pragma unroll
    for (int it = 0; it < 4; ++it) {
        float4 v0 = *reinterpret_cast<const float4*>(q + (size_t)(it * 8 + 0) * W_);
        float4 v1 = *reinterpret_cast<const float4*>(q + (size_t)(it * 8 + 2) * W_);
        float4 v2 = *reinterpret_cast<const float4*>(q + (size_t)(it * 8 + 4) * W_);
        float4 v3 = *reinterpret_cast<const float4*>(q + (size_t)(it * 8 + 6) * W_);
        a0 += (v0.x + v0.y) + (v0.z + v0.w);
        a1 += (v1.x + v1.y) + (v1.z + v1.w);
        a2 += (v2.x + v2.y) + (v2.z + v2.w);
        a3 += (v3.x + v3.y) + (v3.z + v3.w);
    }
    float acc = (a0 + a1) + (a2 + a3);
#pragma unroll
    for (int off = 16; off > 0; off >>= 1)
        acc += __shfl_down_sync(0xFFFFFFFFu, acc, off);
    if (lane == 0) {
        float* dst = half ? g_ph1 : g_ph0;
        dst[b * GC_ + ij * C_ + c] = acc;   // raw sum; /4096 in mlp1
    }
}

// ---------------------------------------------------------------------------
// K1: pool first group (half patches). grid = nb*256 blocks.
// ---------------------------------------------------------------------------
__global__ void __launch_bounds__(NT) se4_pool0(const float* __restrict__ t) {
    pool_half_warp(t, 0, blockIdx.x * 8 + (threadIdx.x >> 5), threadIdx.x & 31);
}

// ---------------------------------------------------------------------------
// K: mlp stage 1 for batches [b0, b0+nb). One warp per (b,out). grid = nb*32.
// ---------------------------------------------------------------------------
__global__ void __launch_bounds__(NT) se4_mlp1(const float* __restrict__ reduce_w,
                                               const float* __restrict__ reduce_b,
                                               int b0) {
    int lw   = blockIdx.x * 8 + (threadIdx.x >> 5);
    int lane = threadIdx.x & 31;
    int b    = b0 + (lw >> 8);
    int out  = lw & 255;

    const float4* wrow = reinterpret_cast<const float4*>(reduce_w + (size_t)out * GC_);
    const float4* p0   = reinterpret_cast<const float4*>(g_ph0 + (size_t)b * GC_);
    const float4* p1   = reinterpret_cast<const float4*>(g_ph1 + (size_t)b * GC_);

    float acc = 0.0f;
#pragma unroll
    for (int k4 = lane; k4 < GC_ / 4; k4 += 32) {
        float4 wv = wrow[k4];
        float4 x0 = p0[k4];
        float4 x1 = p1[k4];
        acc += wv.x * (x0.x + x1.x) + wv.y * (x0.y + x1.y)
             + wv.z * (x0.z + x1.z) + wv.w * (x0.w + x1.w);
    }
#pragma unroll
    for (int off = 16; off > 0; off >>= 1)
        acc += __shfl_down_sync(0xFFFFFFFFu, acc, off);
    if (lane == 0)
        g_s[b * SQ_ + out] = mishf(acc * (1.0f / 4096.0f) + reduce_b[out]);
}

// ---------------------------------------------------------------------------
// K: mlp stage 2 for batches [b0, b0+nb). One warp per (b,out). grid = nb*128.
// ---------------------------------------------------------------------------
__global__ void __launch_bounds__(NT) se4_mlp2(const float* __restrict__ expand_w,
                                               const float* __restrict__ expand_b,
                                               int b0) {
    int lw   = blockIdx.x * 8 + (threadIdx.x >> 5);
    int lane = threadIdx.x & 31;
    int b    = b0 + (lw >> 10);
    int out  = lw & 1023;

    const float4* wrow = reinterpret_cast<const float4*>(expand_w + (size_t)out * SQ_);
    const float4* srow = reinterpret_cast<const float4*>(g_s + (size_t)b * SQ_);

    float acc = 0.0f;
#pragma unroll
    for (int k4 = lane; k4 < SQ_ / 4; k4 += 32) {
        float4 wv = wrow[k4];
        float4 sv = srow[k4];
        acc += wv.x * sv.x + wv.y * sv.y + wv.z * sv.z + wv.w * sv.w;
    }
#pragma unroll
    for (int off = 16; off > 0; off >>= 1)
        acc += __shfl_down_sync(0xFFFFFFFFu, acc, off);
    if (lane == 0)
        g_gates[b * GC_ + out] = sigmoidf_(acc + expand_b[out]);
}

// ---------------------------------------------------------------------------
// K: gatepool — two independent roles, no synchronization.
//   blocks [0, pool_nb*256): pool batches [pool_b0, ..) half-patches (default
//     cache policy -> fills L2 for the NEXT gatepool kernel)
//   blocks [pool_nb*256, gridDim.x): gate batches [gate_b0, ..). One 64B
//     chunk (4 consecutive float4, single gate value) per thread-iteration.
//     Reads .cs (L2-resident, demote after use), writes .stcs (streaming).
// ---------------------------------------------------------------------------
__global__ void __launch_bounds__(NT) se4_gatepool(const float* __restrict__ t,
                                                   float* __restrict__ out,
                                                   int gate_b0, int gate_nb,
                                                   int pool_b0, int pool_nb) {
    int poolBlocks = pool_nb * 256;

    if ((int)blockIdx.x < poolBlocks) {
        pool_half_warp(t, pool_b0, blockIdx.x * 8 + (threadIdx.x >> 5),
                       threadIdx.x & 31);
        return;
    }

    // ---- gate role ----
    int gb = blockIdx.x - poolBlocks;
    int gateBlocks = gridDim.x - poolBlocks;
    const float4* tb = reinterpret_cast<const float4*>(t)  + (size_t)gate_b0 * BATCH_F4;
    float4*       ob = reinterpret_cast<float4*>(out)      + (size_t)gate_b0 * BATCH_F4;
    const float*  gbase = g_gates + gate_b0 * GC_;
    const size_t total_chunks = (size_t)gate_nb * (BATCH_F4 / 4);
    const size_t S = (size_t)gateBlocks * NT;

    for (size_t ch = (size_t)gb * NT + threadIdx.x; ch < total_chunks; ch += S) {
        size_t b4 = ch * 4;                 // float4 index of chunk start
        // layout of b4: [b_local][c(6)][h(8)][w4(6)]; whole chunk shares gate
        int w4 = (int)(b4 & 63);
        int h  = (int)(b4 >> 6) & 255;
        int c  = (int)(b4 >> 14) & 63;
        int bl = (int)(b4 >> 20);
        float gg = __ldg(gbase + bl * 1024 + (h >> 6) * 256 + (w4 >> 4) * 64 + c);

        float4 v0 = __ldcs(tb + b4 + 0);
        float4 v1 = __ldcs(tb + b4 + 1);
        float4 v2 = __ldcs(tb + b4 + 2);
        float4 v3 = __ldcs(tb + b4 + 3);
        v0.x *= gg; v0.y *= gg; v0.z *= gg; v0.w *= gg;
        v1.x *= gg; v1.y *= gg; v1.z *= gg; v1.w *= gg;
        v2.x *= gg; v2.y *= gg; v2.z *= gg; v2.w *= gg;
        v3.x *= gg; v3.y *= gg; v3.z *= gg; v3.w *= gg;
        __stcs(ob + b4 + 0, v0);
        __stcs(ob + b4 + 1, v1);
        __stcs(ob + b4 + 2, v2);
        __stcs(ob + b4 + 3, v3);
    }
}

// ---------------------------------------------------------------------------
extern "C" void kernel_launch(void* const* d_in, const int* in_sizes, int n_in,
                              void* d_out, int out_size) {
    const float* t        = (const float*)d_in[0];
    const float* reduce_w = (const float*)d_in[1];
    const float* reduce_b = (const float*)d_in[2];
    const float* expand_w = (const float*)d_in[3];
    const float* expand_b = (const float*)d_in[4];
    float* out = (float*)d_out;

    // Groups: G0 = {0,1,2}, G1 = {3,4,5}, G2 = {6,7}
    se4_pool0<<<3 * 256, NT>>>(t);
    se4_mlp1<<<3 * 32,  NT>>>(reduce_w, reduce_b, 0);
    se4_mlp2<<<3 * 128, NT>>>(expand_w, expand_b, 0);

    se4_gatepool<<<3 * 256 + 1280, NT>>>(t, out, 0, 3, 3, 3);
    se4_mlp1<<<3 * 32,  NT>>>(reduce_w, reduce_b, 3);
    se4_mlp2<<<3 * 128, NT>>>(expand_w, expand_b, 3);

    se4_gatepool<<<2 * 256 + 1280, NT>>>(t, out, 3, 3, 6, 2);
    se4_mlp1<<<2 * 32,  NT>>>(reduce_w, reduce_b, 6);
    se4_mlp2<<<2 * 128, NT>>>(expand_w, expand_b, 6);

    se4_gatepool<<<1536, NT>>>(t, out, 6, 2, 0, 0);
}

// round 9
// speedup vs baseline: 1.5325x; 1.1529x over previous
#include <cuda_runtime.h>
#include <math.h>

// ---------------------------------------------------------------------------
// SE4: 4x4-patch squeeze-excite, serial group pipeline for L2 reuse.
//   t: [B=8, C=64, H=256, W=256] fp32 (134 MB), L2 = 126 MB.
//   Groups: A = batches 0-3 (67 MB), B = batches 4-7 (67 MB).
//   pool(A); mlp1(A); mlp2(A); pool(B); gate(A); mlp1(B); mlp2(B); gate(B)
//   gate(X) reads t(X) from L2 (pooled earlier, still resident), .cs demote,
//   and streams its writes (.stcs). DRAM ~= 268-290 MB vs 402 MB two-pass.
//   All kernels are pure single-role bodies (mixed-role kernels measured
//   15-20% slower per byte; intra-kernel spins catastrophically slower).
// ---------------------------------------------------------------------------

#define B_   8
#define C_   64
#define H_   256
#define W_   256
#define SQ_  256
#define GC_  1024
#define NPOOL (B_ * GC_)
#define NT   256
#define BATCH_F4 (C_ * H_ * W_ / 4)       // 2^20 float4 per batch

__device__ float g_ph0[NPOOL];      // half-patch raw sums (rows 0-31)
__device__ float g_ph1[NPOOL];      // half-patch raw sums (rows 32-63)
__device__ float g_s[B_ * SQ_];
__device__ float g_gates[NPOOL];

// ---------------------------------------------------------------------------
__device__ __forceinline__ float mishf(float x) {
    float sp = (x > 20.0f) ? x : log1pf(__expf(x));
    return x * tanhf(sp);
}
__device__ __forceinline__ float sigmoidf_(float x) {
    return 1.0f / (1.0f + __expf(-x));
}

// ---------------------------------------------------------------------------
// Pool: one half-patch (32 rows x 64 cols) per warp, 4 batches per launch.
// grid = 4*2048/8 = 1024 blocks. Default cache policy (lines stay in L2).
// ---------------------------------------------------------------------------
__global__ void __launch_bounds__(NT) se4_pool(const float* __restrict__ t, int b0) {
    int pw   = blockIdx.x * 8 + (threadIdx.x >> 5);   // 0..8191
    int lane = threadIdx.x & 31;

    int b    = b0 + (pw >> 11);
    int rem  = pw & 2047;
    int half = rem & 1;
    int p    = rem >> 1;            // 0..1023
    int c    = p >> 4;
    int ij   = p & 15;
    int i    = ij >> 2;
    int j    = ij & 3;

    const float* base = t + (((size_t)(b * C_ + c) * H_ + i * 64 + half * 32) * W_ + j * 64);
    const float* q = base + (size_t)(lane >> 4) * W_ + (lane & 15) * 4;

    float a0 = 0.f, a1 = 0.f, a2 = 0.f, a3 = 0.f;
#pragma unroll
    for (int it = 0; it < 4; ++it) {
        float4 v0 = *reinterpret_cast<const float4*>(q + (size_t)(it * 8 + 0) * W_);
        float4 v1 = *reinterpret_cast<const float4*>(q + (size_t)(it * 8 + 2) * W_);
        float4 v2 = *reinterpret_cast<const float4*>(q + (size_t)(it * 8 + 4) * W_);
        float4 v3 = *reinterpret_cast<const float4*>(q + (size_t)(it * 8 + 6) * W_);
        a0 += (v0.x + v0.y) + (v0.z + v0.w);
        a1 += (v1.x + v1.y) + (v1.z + v1.w);
        a2 += (v2.x + v2.y) + (v2.z + v2.w);
        a3 += (v3.x + v3.y) + (v3.z + v3.w);
    }
    float acc = (a0 + a1) + (a2 + a3);
#pragma unroll
    for (int off = 16; off > 0; off >>= 1)
        acc += __shfl_down_sync(0xFFFFFFFFu, acc, off);
    if (lane == 0) {
        float* dst = half ? g_ph1 : g_ph0;
        dst[b * GC_ + ij * C_ + c] = acc;   // raw sum; /4096 in mlp1
    }
}

// ---------------------------------------------------------------------------
// mlp1: one warp per (b,out), 4 batches. grid = 4*256/8 = 128 blocks.
// ---------------------------------------------------------------------------
__global__ void __launch_bounds__(NT) se4_mlp1(const float* __restrict__ reduce_w,
                                               const float* __restrict__ reduce_b,
                                               int b0) {
    int lw   = blockIdx.x * 8 + (threadIdx.x >> 5);
    int lane = threadIdx.x & 31;
    int b    = b0 + (lw >> 8);
    int out  = lw & 255;

    const float4* wrow = reinterpret_cast<const float4*>(reduce_w + (size_t)out * GC_);
    const float4* p0   = reinterpret_cast<const float4*>(g_ph0 + (size_t)b * GC_);
    const float4* p1   = reinterpret_cast<const float4*>(g_ph1 + (size_t)b * GC_);

    float acc = 0.0f;
#pragma unroll
    for (int k4 = lane; k4 < GC_ / 4; k4 += 32) {
        float4 wv = wrow[k4];
        float4 x0 = p0[k4];
        float4 x1 = p1[k4];
        acc += wv.x * (x0.x + x1.x) + wv.y * (x0.y + x1.y)
             + wv.z * (x0.z + x1.z) + wv.w * (x0.w + x1.w);
    }
#pragma unroll
    for (int off = 16; off > 0; off >>= 1)
        acc += __shfl_down_sync(0xFFFFFFFFu, acc, off);
    if (lane == 0)
        g_s[b * SQ_ + out] = mishf(acc * (1.0f / 4096.0f) + reduce_b[out]);
}

// ---------------------------------------------------------------------------
// mlp2: one warp per (b,out), 4 batches. grid = 4*1024/8 = 512 blocks.
// ---------------------------------------------------------------------------
__global__ void __launch_bounds__(NT) se4_mlp2(const float* __restrict__ expand_w,
                                               const float* __restrict__ expand_b,
                                               int b0) {
    int lw   = blockIdx.x * 8 + (threadIdx.x >> 5);
    int lane = threadIdx.x & 31;
    int b    = b0 + (lw >> 10);
    int out  = lw & 1023;

    const float4* wrow = reinterpret_cast<const float4*>(expand_w + (size_t)out * SQ_);
    const float4* srow = reinterpret_cast<const float4*>(g_s + (size_t)b * SQ_);

    float acc = 0.0f;
#pragma unroll
    for (int k4 = lane; k4 < SQ_ / 4; k4 += 32) {
        float4 wv = wrow[k4];
        float4 sv = srow[k4];
        acc += wv.x * sv.x + wv.y * sv.y + wv.z * sv.z + wv.w * sv.w;
    }
#pragma unroll
    for (int off = 16; off > 0; off >>= 1)
        acc += __shfl_down_sync(0xFFFFFFFFu, acc, off);
    if (lane == 0)
        g_gates[b * GC_ + out] = sigmoidf_(acc + expand_b[out]);
}

// ---------------------------------------------------------------------------
// Gate: one consecutive float4 per thread (round-3 body, regs ~16, fully
// coalesced). Exact grid = 4*BATCH_F4/NT = 16384 blocks, no stride loop.
// Reads .cs (L2-resident from earlier pool, demote after use);
// writes .stcs (streaming, don't thrash L2).
// ---------------------------------------------------------------------------
__global__ void __launch_bounds__(NT) se4_gate(const float* __restrict__ t,
                                               float* __restrict__ out,
                                               int b0) {
    size_t idx4 = (size_t)blockIdx.x * NT + threadIdx.x;  // within group
    // layout: [b_local(2)][c(6)][h(8)][w4(6)]
    int w4 = (int)(idx4 & 63);
    int h  = (int)(idx4 >> 6) & 255;
    int c  = (int)(idx4 >> 14) & 63;
    int bl = (int)(idx4 >> 20);

    float gate = __ldg(&g_gates[(b0 + bl) * GC_ + (h >> 6) * 256 + (w4 >> 4) * 64 + c]);

    const float4* tb = reinterpret_cast<const float4*>(t)  + (size_t)b0 * BATCH_F4;
    float4*       ob = reinterpret_cast<float4*>(out)      + (size_t)b0 * BATCH_F4;

    float4 v = __ldcs(tb + idx4);
    v.x *= gate; v.y *= gate; v.z *= gate; v.w *= gate;
    __stcs(ob + idx4, v);
}

// ---------------------------------------------------------------------------
extern "C" void kernel_launch(void* const* d_in, const int* in_sizes, int n_in,
                              void* d_out, int out_size) {
    const float* t        = (const float*)d_in[0];
    const float* reduce_w = (const float*)d_in[1];
    const float* reduce_b = (const float*)d_in[2];
    const float* expand_w = (const float*)d_in[3];
    const float* expand_b = (const float*)d_in[4];
    float* out = (float*)d_out;

    // Group A = batches 0-3, Group B = batches 4-7.
    se4_pool<<<1024, NT>>>(t, 0);               // A -> L2
    se4_mlp1<<<128,  NT>>>(reduce_w, reduce_b, 0);
    se4_mlp2<<<512,  NT>>>(expand_w, expand_b, 0);
    se4_pool<<<1024, NT>>>(t, 4);               // B -> L2 (beside A)
    se4_gate<<<16384, NT>>>(t, out, 0);         // A from L2, stream writes
    se4_mlp1<<<128,  NT>>>(reduce_w, reduce_b, 4);
    se4_mlp2<<<512,  NT>>>(expand_w, expand_b, 4);
    se4_gate<<<16384, NT>>>(t, out, 4);         // B from L2, stream writes
}